// round 2
// baseline (speedup 1.0000x reference)
#include <cuda_runtime.h>
#include <math.h>

#define N_TOK 2048
#define BATCH 2
#define DIM   1024
#define NHEAD 16
#define DHEAD 64
#define MROWS (BATCH * N_TOK)   // 4096
#define RMS_EPS 1.1920929e-07f

// ---------------- scratch (static __device__ — no allocation) ----------------
__device__ float g_xn[MROWS * DIM];
__device__ float g_q [MROWS * DIM];
__device__ float g_k [MROWS * DIM];
__device__ float g_v [MROWS * DIM];
__device__ float g_ao[MROWS * DIM];
__device__ float g_cos[N_TOK * (DHEAD / 2)];
__device__ float g_sin[N_TOK * (DHEAD / 2)];

// ---------------- RoPE cos/sin table (fp64 trig: robust vs fast-math) --------
__global__ void rope_table_kernel() {
    int idx = blockIdx.x * blockDim.x + threadIdx.x;   // t*32 + i
    if (idx >= N_TOK * 32) return;
    int t = idx >> 5;
    int i = idx & 31;
    double invf_d = pow(10000.0, -(double)(2 * i) / 64.0);
    float  invf   = (float)invf_d;                 // mimic fp32 inv_freq
    float  ang    = (float)t * invf;               // fp32 angle like reference
    g_cos[idx] = (float)cos((double)ang);
    g_sin[idx] = (float)sin((double)ang);
}

// ---------------- RMSNorm: one block per row ---------------------------------
__global__ __launch_bounds__(256) void rmsnorm_kernel(
    const float* __restrict__ x, const float* __restrict__ w, float* __restrict__ y)
{
    int row = blockIdx.x;
    const float4* xr = (const float4*)(x + (size_t)row * DIM);
    float4 v4 = xr[threadIdx.x];                   // 256 threads * 4 = 1024
    float ss = v4.x * v4.x + v4.y * v4.y + v4.z * v4.z + v4.w * v4.w;
    #pragma unroll
    for (int o = 16; o; o >>= 1) ss += __shfl_xor_sync(0xFFFFFFFFu, ss, o);
    __shared__ float sred[8];
    int lane = threadIdx.x & 31, wid = threadIdx.x >> 5;
    if (lane == 0) sred[wid] = ss;
    __syncthreads();
    if (wid == 0) {
        float t = (lane < 8) ? sred[lane] : 0.f;
        #pragma unroll
        for (int o = 4; o; o >>= 1) t += __shfl_xor_sync(0xFFFFFFFFu, t, o);
        if (lane == 0) sred[0] = t;
    }
    __syncthreads();
    float scale = rsqrtf(sred[0] * (1.0f / (float)DIM) + RMS_EPS);
    const float4* wr = (const float4*)w;
    float4 wv = wr[threadIdx.x];
    float4 o4;
    o4.x = v4.x * scale * wv.x;
    o4.y = v4.y * scale * wv.y;
    o4.z = v4.z * scale * wv.z;
    o4.w = v4.w * scale * wv.w;
    ((float4*)(y + (size_t)row * DIM))[threadIdx.x] = o4;
}

// ---------------- fp32 NT GEMM: C[m,n] = sum_d A[m,d]*B[n,d] -----------------
// A: [M,1024] row-major, B: [1024,1024] row-major (weights), C: [M,1024]
#define BM 64
#define BN 64
#define BK 16
__global__ __launch_bounds__(256) void gemm_nt(
    const float* __restrict__ A, const float* __restrict__ B, float* __restrict__ C)
{
    __shared__ float As[BK][BM];   // k-outer: inner-loop LDS.128 conflict-free
    __shared__ float Bs[BK][BN];
    int bm = blockIdx.y * BM;
    int bn = blockIdx.x * BN;
    int tid = threadIdx.x;
    int tx = tid & 15, ty = tid >> 4;

    float acc[4][4];
    #pragma unroll
    for (int i = 0; i < 4; i++)
        #pragma unroll
        for (int j = 0; j < 4; j++) acc[i][j] = 0.f;

    int lrow = tid >> 2;             // 0..63
    int lk4  = (tid & 3) * 4;        // 0,4,8,12
    const float* Ag = A + (size_t)(bm + lrow) * DIM + lk4;
    const float* Bg = B + (size_t)(bn + lrow) * DIM + lk4;

    for (int k0 = 0; k0 < DIM; k0 += BK) {
        float4 av = *(const float4*)(Ag + k0);
        float4 bv = *(const float4*)(Bg + k0);
        As[lk4 + 0][lrow] = av.x; As[lk4 + 1][lrow] = av.y;
        As[lk4 + 2][lrow] = av.z; As[lk4 + 3][lrow] = av.w;
        Bs[lk4 + 0][lrow] = bv.x; Bs[lk4 + 1][lrow] = bv.y;
        Bs[lk4 + 2][lrow] = bv.z; Bs[lk4 + 3][lrow] = bv.w;
        __syncthreads();
        #pragma unroll
        for (int kk = 0; kk < BK; kk++) {
            float4 a = *(const float4*)&As[kk][ty * 4];
            float4 b = *(const float4*)&Bs[kk][tx * 4];
            acc[0][0] += a.x * b.x; acc[0][1] += a.x * b.y; acc[0][2] += a.x * b.z; acc[0][3] += a.x * b.w;
            acc[1][0] += a.y * b.x; acc[1][1] += a.y * b.y; acc[1][2] += a.y * b.z; acc[1][3] += a.y * b.w;
            acc[2][0] += a.z * b.x; acc[2][1] += a.z * b.y; acc[2][2] += a.z * b.z; acc[2][3] += a.z * b.w;
            acc[3][0] += a.w * b.x; acc[3][1] += a.w * b.y; acc[3][2] += a.w * b.z; acc[3][3] += a.w * b.w;
        }
        __syncthreads();
    }
    #pragma unroll
    for (int i = 0; i < 4; i++) {
        float4 o4 = make_float4(acc[i][0], acc[i][1], acc[i][2], acc[i][3]);
        *(float4*)(C + (size_t)(bm + ty * 4 + i) * DIM + bn + tx * 4) = o4;
    }
}

// ---------------- RoPE in-place (optionally fused q scale) -------------------
__global__ void rope_kernel(float* __restrict__ qk, float qscale) {
    int idx = blockIdx.x * blockDim.x + threadIdx.x;  // pair index over MROWS*512
    if (idx >= MROWS * (DIM / 2)) return;
    int row = idx / (DIM / 2);
    int p   = idx % (DIM / 2);       // p = h*32 + j
    int pos = row & (N_TOK - 1);
    int i   = p & 31;                // freq index within head
    float c = g_cos[pos * 32 + i];
    float s = g_sin[pos * 32 + i];
    float2* ptr = (float2*)qk + idx;
    float2 v = *ptr;
    float e = (v.x * c - v.y * s) * qscale;
    float o = (v.y * c + v.x * s) * qscale;
    *ptr = make_float2(e, o);
}

// ---------------- fp32 causal flash attention --------------------------------
// layout: [b, n, h, d] row-major (== [4096, 1024]). 1 thread = 1 query row.
#define TJ 32
#define BQ 128
__global__ __launch_bounds__(128) void flash_kernel(
    const float* __restrict__ Q, const float* __restrict__ K,
    const float* __restrict__ V, float* __restrict__ O)
{
    __shared__ float Ks[TJ][DHEAD];
    __shared__ float Vs[TJ][DHEAD];
    int bh = blockIdx.x;             // 0..31
    int b  = bh >> 4, h = bh & 15;
    int r0 = (gridDim.y - 1 - blockIdx.y) * BQ;  // heavy blocks first
    int i  = r0 + threadIdx.x;

    float q[DHEAD];
    #pragma unroll
    for (int d4 = 0; d4 < DHEAD / 4; d4++) {
        float4 t = *(const float4*)(Q + (size_t)(b * N_TOK + i) * DIM + h * DHEAD + d4 * 4);
        q[4 * d4 + 0] = t.x; q[4 * d4 + 1] = t.y; q[4 * d4 + 2] = t.z; q[4 * d4 + 3] = t.w;
    }
    float o[DHEAD];
    #pragma unroll
    for (int d = 0; d < DHEAD; d++) o[d] = 0.f;
    float m = -1e30f, l = 0.f;

    int jend = r0 + BQ;
    for (int j0 = 0; j0 < jend; j0 += TJ) {
        #pragma unroll
        for (int t4 = 0; t4 < (TJ * DHEAD / 4) / 128; t4++) {   // 4 float4 per thread
            int f  = threadIdx.x + t4 * 128;
            int rj = f >> 4;
            int c4 = (f & 15) * 4;
            size_t g = (size_t)(b * N_TOK + j0 + rj) * DIM + h * DHEAD + c4;
            *(float4*)&Ks[rj][c4] = *(const float4*)(K + g);
            *(float4*)&Vs[rj][c4] = *(const float4*)(V + g);
        }
        __syncthreads();

        float s[TJ];
        float tm = -1e30f;
        #pragma unroll
        for (int jj = 0; jj < TJ; jj++) {
            float d0 = 0.f, d1 = 0.f, d2 = 0.f, d3 = 0.f;
            #pragma unroll
            for (int d = 0; d < DHEAD; d += 4) {
                float4 kv = *(const float4*)&Ks[jj][d];
                d0 += q[d + 0] * kv.x; d1 += q[d + 1] * kv.y;
                d2 += q[d + 2] * kv.z; d3 += q[d + 3] * kv.w;
            }
            float sv = (d0 + d1) + (d2 + d3);
            sv = (j0 + jj <= i) ? sv : -1e30f;   // causal mask
            s[jj] = sv;
            tm = fmaxf(tm, sv);
        }
        float mn = fmaxf(m, tm);
        float sc = __expf(m - mn);
        l *= sc;
        #pragma unroll
        for (int d = 0; d < DHEAD; d++) o[d] *= sc;
        #pragma unroll
        for (int jj = 0; jj < TJ; jj++) {
            float p = __expf(s[jj] - mn);
            l += p;
            #pragma unroll
            for (int d = 0; d < DHEAD; d += 4) {
                float4 vv = *(const float4*)&Vs[jj][d];
                o[d + 0] += p * vv.x; o[d + 1] += p * vv.y;
                o[d + 2] += p * vv.z; o[d + 3] += p * vv.w;
            }
        }
        m = mn;
        __syncthreads();
    }
    float inv = 1.f / l;
    #pragma unroll
    for (int d4 = 0; d4 < 16; d4++) {
        float4 t = make_float4(o[4 * d4] * inv, o[4 * d4 + 1] * inv,
                               o[4 * d4 + 2] * inv, o[4 * d4 + 3] * inv);
        *(float4*)(O + (size_t)(b * N_TOK + i) * DIM + h * DHEAD + 4 * d4) = t;
    }
}

// ---------------- launch -----------------------------------------------------
extern "C" void kernel_launch(void* const* d_in, const int* in_sizes, int n_in,
                              void* d_out, int out_size)
{
    const float* tokens = (const float*)d_in[0];
    const float* normw  = (const float*)d_in[1];
    const float* wq     = (const float*)d_in[2];
    const float* wk     = (const float*)d_in[3];
    const float* wv     = (const float*)d_in[4];
    const float* wo     = (const float*)d_in[5];
    float* out = (float*)d_out;

    float *xn, *q, *k, *v, *ao;
    cudaGetSymbolAddress((void**)&xn, g_xn);
    cudaGetSymbolAddress((void**)&q,  g_q);
    cudaGetSymbolAddress((void**)&k,  g_k);
    cudaGetSymbolAddress((void**)&v,  g_v);
    cudaGetSymbolAddress((void**)&ao, g_ao);

    rope_table_kernel<<<256, 256>>>();                       // 65536 threads
    rmsnorm_kernel<<<MROWS, 256>>>(tokens, normw, xn);

    dim3 ggrid(DIM / BN, MROWS / BM);                        // (16, 64)
    gemm_nt<<<ggrid, 256>>>(xn, wq, q);
    gemm_nt<<<ggrid, 256>>>(xn, wk, k);
    gemm_nt<<<ggrid, 256>>>(xn, wv, v);

    int npairs = MROWS * (DIM / 2);
    rope_kernel<<<(npairs + 255) / 256, 256>>>(q, 0.125f);   // 64^-0.5 fused
    rope_kernel<<<(npairs + 255) / 256, 256>>>(k, 1.0f);

    flash_kernel<<<dim3(BATCH * NHEAD, N_TOK / BQ), 128>>>(q, k, v, ao);

    gemm_nt<<<ggrid, 256>>>(ao, wo, out);
}

// round 4
// speedup vs baseline: 1.6853x; 1.6853x over previous
#include <cuda_runtime.h>
#include <cuda_bf16.h>
#include <math.h>
#include <stdint.h>

#define N_TOK 2048
#define BATCH 2
#define DIM   1024
#define NHEAD 16
#define DHEAD 64
#define MROWS (BATCH * N_TOK)   // 4096
#define RMS_EPS 1.1920929e-07f

// ---------------- scratch (static __device__ — no allocation) ----------------
__device__ __nv_bfloat16 g_xh [MROWS * DIM];
__device__ __nv_bfloat16 g_xl [MROWS * DIM];
__device__ float         g_q  [MROWS * DIM];
__device__ float         g_k  [MROWS * DIM];
__device__ float         g_v  [MROWS * DIM];
__device__ __nv_bfloat16 g_aoh[MROWS * DIM];
__device__ __nv_bfloat16 g_aol[MROWS * DIM];
__device__ __nv_bfloat16 g_wqh[DIM * DIM], g_wql[DIM * DIM];
__device__ __nv_bfloat16 g_wkh[DIM * DIM], g_wkl[DIM * DIM];
__device__ __nv_bfloat16 g_wvh[DIM * DIM], g_wvl[DIM * DIM];
__device__ __nv_bfloat16 g_woh[DIM * DIM], g_wol[DIM * DIM];
__device__ float g_cos[N_TOK * (DHEAD / 2)];
__device__ float g_sin[N_TOK * (DHEAD / 2)];

// ---------------- helpers ----------------------------------------------------
__device__ __forceinline__ uint32_t smem_u32(const void* p) {
    uint32_t a;
    asm("{ .reg .u64 t; cvta.to.shared.u64 t, %1; cvt.u32.u64 %0, t; }" : "=r"(a) : "l"(p));
    return a;
}
__device__ __forceinline__ void cp_async16(uint32_t dst, const void* src) {
    asm volatile("cp.async.cg.shared.global [%0], [%1], 16;" :: "r"(dst), "l"(src));
}
#define CP_COMMIT() asm volatile("cp.async.commit_group;" ::: "memory")
#define CP_WAIT0()  asm volatile("cp.async.wait_group 0;" ::: "memory")

__device__ __forceinline__ void ldmatrix_x4(uint32_t& r0, uint32_t& r1,
                                            uint32_t& r2, uint32_t& r3, uint32_t addr) {
    asm volatile("ldmatrix.sync.aligned.m8n8.x4.shared.b16 {%0,%1,%2,%3}, [%4];"
                 : "=r"(r0), "=r"(r1), "=r"(r2), "=r"(r3) : "r"(addr));
}
__device__ __forceinline__ void mma_bf16(float* d, const uint32_t* a, const uint32_t* b) {
    asm volatile(
        "mma.sync.aligned.m16n8k16.row.col.f32.bf16.bf16.f32 "
        "{%0,%1,%2,%3}, {%4,%5,%6,%7}, {%8,%9}, {%0,%1,%2,%3};"
        : "+f"(d[0]), "+f"(d[1]), "+f"(d[2]), "+f"(d[3])
        : "r"(a[0]), "r"(a[1]), "r"(a[2]), "r"(a[3]), "r"(b[0]), "r"(b[1]));
}

// fp32 -> (hi,lo) bf16 split
__device__ __forceinline__ void split2(float x, __nv_bfloat16& h, __nv_bfloat16& l) {
    h = __float2bfloat16(x);
    l = __float2bfloat16(x - __bfloat162float(h));
}
struct alignas(8) BF4 { __nv_bfloat16 v[4]; };

// ---------------- RoPE cos/sin table (fp64 trig: robust) ---------------------
__global__ void rope_table_kernel() {
    int idx = blockIdx.x * blockDim.x + threadIdx.x;   // t*32 + i
    if (idx >= N_TOK * 32) return;
    int t = idx >> 5;
    int i = idx & 31;
    double invf_d = pow(10000.0, -(double)(2 * i) / 64.0);
    float  invf   = (float)invf_d;
    float  ang    = (float)t * invf;
    g_cos[idx] = (float)cos((double)ang);
    g_sin[idx] = (float)sin((double)ang);
}

// ---------------- RMSNorm fused with bf16 hi/lo split ------------------------
__global__ __launch_bounds__(256) void rmsnorm_split_kernel(
    const float* __restrict__ x, const float* __restrict__ w)
{
    int row = blockIdx.x;
    const float4* xr = (const float4*)(x + (size_t)row * DIM);
    float4 v4 = xr[threadIdx.x];
    float ss = v4.x * v4.x + v4.y * v4.y + v4.z * v4.z + v4.w * v4.w;
    #pragma unroll
    for (int o = 16; o; o >>= 1) ss += __shfl_xor_sync(0xFFFFFFFFu, ss, o);
    __shared__ float sred[8];
    int lane = threadIdx.x & 31, wid = threadIdx.x >> 5;
    if (lane == 0) sred[wid] = ss;
    __syncthreads();
    if (wid == 0) {
        float t = (lane < 8) ? sred[lane] : 0.f;
        #pragma unroll
        for (int o = 4; o; o >>= 1) t += __shfl_xor_sync(0xFFFFFFFFu, t, o);
        if (lane == 0) sred[0] = t;
    }
    __syncthreads();
    float scale = rsqrtf(sred[0] * (1.0f / (float)DIM) + RMS_EPS);
    float4 wv = ((const float4*)w)[threadIdx.x];
    float o0 = v4.x * scale * wv.x, o1 = v4.y * scale * wv.y;
    float o2 = v4.z * scale * wv.z, o3 = v4.w * scale * wv.w;
    BF4 hb, lb;
    split2(o0, hb.v[0], lb.v[0]); split2(o1, hb.v[1], lb.v[1]);
    split2(o2, hb.v[2], lb.v[2]); split2(o3, hb.v[3], lb.v[3]);
    size_t base = (size_t)row * DIM + threadIdx.x * 4;
    *(BF4*)&g_xh[base] = hb;
    *(BF4*)&g_xl[base] = lb;
}

// ---------------- weight fp32 -> hi/lo bf16 split -----------------------------
__global__ __launch_bounds__(256) void split_w_kernel(
    const float* __restrict__ w, __nv_bfloat16* __restrict__ wh, __nv_bfloat16* __restrict__ wl)
{
    int idx = blockIdx.x * blockDim.x + threadIdx.x;   // float4 index
    float4 v4 = ((const float4*)w)[idx];
    BF4 hb, lb;
    split2(v4.x, hb.v[0], lb.v[0]); split2(v4.y, hb.v[1], lb.v[1]);
    split2(v4.z, hb.v[2], lb.v[2]); split2(v4.w, hb.v[3], lb.v[3]);
    *(BF4*)&wh[(size_t)idx * 4] = hb;
    *(BF4*)&wl[(size_t)idx * 4] = lb;
}

// ---------------- HMMA split-bf16 NT GEMM ------------------------------------
// C[m,n] = sum_d A[m,d]*B[n,d]; A,B as hi/lo bf16, K=1024.
// CTA tile 128x128, k-chunk 32, double-buffered cp.async.
#define KC      32
#define ROWB    80                       // 64B row + 16B pad (conflict-free ldmatrix)
#define OPTILE  (128 * ROWB)             // 10240 B
#define STAGEB  (4 * OPTILE)             // Ah, Al, Bh, Bl = 40960 B
#define NSTG    2
#define GSMEM_DYN (NSTG * STAGEB)        // 81920 B
#define NCH     (DIM / KC)               // 32

__device__ __forceinline__ void load_stage(
    uint32_t sbase,
    const __nv_bfloat16* __restrict__ Ah, const __nv_bfloat16* __restrict__ Al,
    const __nv_bfloat16* __restrict__ Bh, const __nv_bfloat16* __restrict__ Bl,
    int bm, int bn, int kb, int tid)
{
    const __nv_bfloat16* srcs[4] = { Ah, Al, Bh, Bl };
    #pragma unroll
    for (int op = 0; op < 4; op++) {
        int r0 = (op < 2) ? bm : bn;
        const __nv_bfloat16* s = srcs[op];
        #pragma unroll
        for (int it = 0; it < 2; it++) {
            int i = tid + it * 256;      // 0..511
            int row = i >> 2, ch = i & 3;
            uint32_t dst = sbase + op * OPTILE + row * ROWB + ch * 16;
            cp_async16(dst, s + ((size_t)(r0 + row) * DIM + kb + ch * 8));
        }
    }
    CP_COMMIT();
}

__global__ __launch_bounds__(256, 2) void gemm_tc(
    const __nv_bfloat16* __restrict__ Ah, const __nv_bfloat16* __restrict__ Al,
    const __nv_bfloat16* __restrict__ Bh, const __nv_bfloat16* __restrict__ Bl,
    float* __restrict__ C)
{
    extern __shared__ char smem[];
    uint32_t sm0 = smem_u32(smem);
    int tid = threadIdx.x, wid = tid >> 5, lane = tid & 31;
    int bm = blockIdx.y * 128, bn = blockIdx.x * 128;
    int wm = wid >> 2, wn = wid & 3;           // 2x4 warps: 64x32 warp tiles

    float acc[4][4][4];
    #pragma unroll
    for (int i = 0; i < 4; i++)
        #pragma unroll
        for (int j = 0; j < 4; j++)
            #pragma unroll
            for (int e = 0; e < 4; e++) acc[i][j][e] = 0.f;

    // ldmatrix address components
    int arow = wm * 64 + (lane & 15);           // + mt*16
    int akb  = (lane >> 4) * 16;                // + kk*32
    int brow = wn * 32 + ((lane >> 4) * 8) + (lane & 7);  // + nt2*16
    int bkb  = ((lane >> 3) & 1) * 16;          // + kk*32

    load_stage(sm0, Ah, Al, Bh, Bl, bm, bn, 0, tid);

    for (int c = 0; c < NCH; c++) {
        CP_WAIT0();
        __syncthreads();
        uint32_t sb = sm0 + (c & 1) * STAGEB;
        if (c + 1 < NCH)
            load_stage(sm0 + ((c + 1) & 1) * STAGEB, Ah, Al, Bh, Bl, bm, bn, (c + 1) * KC, tid);

        uint32_t sAh = sb, sAl = sb + OPTILE, sBh = sb + 2 * OPTILE, sBl = sb + 3 * OPTILE;
        #pragma unroll
        for (int kk = 0; kk < 2; kk++) {
            uint32_t ah[4][4], al[4][4], bh[4][2], bl[4][2];
            #pragma unroll
            for (int mt = 0; mt < 4; mt++) {
                uint32_t ao = (uint32_t)((arow + mt * 16) * ROWB + kk * 32 + akb);
                ldmatrix_x4(ah[mt][0], ah[mt][1], ah[mt][2], ah[mt][3], sAh + ao);
                ldmatrix_x4(al[mt][0], al[mt][1], al[mt][2], al[mt][3], sAl + ao);
            }
            #pragma unroll
            for (int p = 0; p < 2; p++) {    // n-tile pairs
                uint32_t bo = (uint32_t)((brow + p * 16) * ROWB + kk * 32 + bkb);
                uint32_t r0, r1, r2, r3;
                ldmatrix_x4(r0, r1, r2, r3, sBh + bo);
                bh[p * 2][0] = r0; bh[p * 2][1] = r1; bh[p * 2 + 1][0] = r2; bh[p * 2 + 1][1] = r3;
                ldmatrix_x4(r0, r1, r2, r3, sBl + bo);
                bl[p * 2][0] = r0; bl[p * 2][1] = r1; bl[p * 2 + 1][0] = r2; bl[p * 2 + 1][1] = r3;
            }
            #pragma unroll
            for (int mt = 0; mt < 4; mt++)
                #pragma unroll
                for (int nt = 0; nt < 4; nt++) {
                    mma_bf16(acc[mt][nt], ah[mt], bh[nt]);
                    mma_bf16(acc[mt][nt], ah[mt], bl[nt]);
                    mma_bf16(acc[mt][nt], al[mt], bh[nt]);
                }
        }
        __syncthreads();
    }

    // epilogue: m16n8 fragment layout
    int r = lane >> 2, cp = (lane & 3) * 2;
    #pragma unroll
    for (int mt = 0; mt < 4; mt++) {
        int gm = bm + wm * 64 + mt * 16 + r;
        #pragma unroll
        for (int nt = 0; nt < 4; nt++) {
            int gc = bn + wn * 32 + nt * 8 + cp;
            *(float2*)(C + (size_t)gm * DIM + gc) =
                make_float2(acc[mt][nt][0], acc[mt][nt][1]);
            *(float2*)(C + (size_t)(gm + 8) * DIM + gc) =
                make_float2(acc[mt][nt][2], acc[mt][nt][3]);
        }
    }
}

// ---------------- RoPE in-place (optionally fused q scale) -------------------
__global__ void rope_kernel(float* __restrict__ qk, float qscale) {
    int idx = blockIdx.x * blockDim.x + threadIdx.x;
    if (idx >= MROWS * (DIM / 2)) return;
    int row = idx / (DIM / 2);
    int p   = idx % (DIM / 2);
    int pos = row & (N_TOK - 1);
    int i   = p & 31;
    float c = g_cos[pos * 32 + i];
    float s = g_sin[pos * 32 + i];
    float2* ptr = (float2*)qk + idx;
    float2 v = *ptr;
    float e = (v.x * c - v.y * s) * qscale;
    float o = (v.y * c + v.x * s) * qscale;
    *ptr = make_float2(e, o);
}

// ---------------- fp32 causal flash attention (split-bf16 output) ------------
#define TJ 32
#define BQ 128
__global__ __launch_bounds__(128) void flash_kernel(
    const float* __restrict__ Q, const float* __restrict__ K,
    const float* __restrict__ V,
    __nv_bfloat16* __restrict__ Oh, __nv_bfloat16* __restrict__ Ol)
{
    __shared__ float Ks[TJ][DHEAD];
    __shared__ float Vs[TJ][DHEAD];
    int bh = blockIdx.x;
    int b  = bh >> 4, h = bh & 15;
    int r0 = (gridDim.y - 1 - blockIdx.y) * BQ;
    int i  = r0 + threadIdx.x;

    float q[DHEAD];
    #pragma unroll
    for (int d4 = 0; d4 < DHEAD / 4; d4++) {
        float4 t = *(const float4*)(Q + (size_t)(b * N_TOK + i) * DIM + h * DHEAD + d4 * 4);
        q[4 * d4 + 0] = t.x; q[4 * d4 + 1] = t.y; q[4 * d4 + 2] = t.z; q[4 * d4 + 3] = t.w;
    }
    float o[DHEAD];
    #pragma unroll
    for (int d = 0; d < DHEAD; d++) o[d] = 0.f;
    float m = -1e30f, l = 0.f;

    int jend = r0 + BQ;
    for (int j0 = 0; j0 < jend; j0 += TJ) {
        #pragma unroll
        for (int t4 = 0; t4 < (TJ * DHEAD / 4) / 128; t4++) {
            int f  = threadIdx.x + t4 * 128;
            int rj = f >> 4;
            int c4 = (f & 15) * 4;
            size_t g = (size_t)(b * N_TOK + j0 + rj) * DIM + h * DHEAD + c4;
            *(float4*)&Ks[rj][c4] = *(const float4*)(K + g);
            *(float4*)&Vs[rj][c4] = *(const float4*)(V + g);
        }
        __syncthreads();

        float s[TJ];
        float tm = -1e30f;
        #pragma unroll
        for (int jj = 0; jj < TJ; jj++) {
            float d0 = 0.f, d1 = 0.f, d2 = 0.f, d3 = 0.f;
            #pragma unroll
            for (int d = 0; d < DHEAD; d += 4) {
                float4 kv = *(const float4*)&Ks[jj][d];
                d0 += q[d + 0] * kv.x; d1 += q[d + 1] * kv.y;
                d2 += q[d + 2] * kv.z; d3 += q[d + 3] * kv.w;
            }
            float sv = (d0 + d1) + (d2 + d3);
            sv = (j0 + jj <= i) ? sv : -1e30f;
            s[jj] = sv;
            tm = fmaxf(tm, sv);
        }
        float mn = fmaxf(m, tm);
        float sc = __expf(m - mn);
        l *= sc;
        #pragma unroll
        for (int d = 0; d < DHEAD; d++) o[d] *= sc;
        #pragma unroll
        for (int jj = 0; jj < TJ; jj++) {
            float p = __expf(s[jj] - mn);
            l += p;
            #pragma unroll
            for (int d = 0; d < DHEAD; d += 4) {
                float4 vv = *(const float4*)&Vs[jj][d];
                o[d + 0] += p * vv.x; o[d + 1] += p * vv.y;
                o[d + 2] += p * vv.z; o[d + 3] += p * vv.w;
            }
        }
        m = mn;
        __syncthreads();
    }
    float inv = 1.f / l;
    size_t obase = (size_t)(b * N_TOK + i) * DIM + h * DHEAD;
    #pragma unroll
    for (int d4 = 0; d4 < 16; d4++) {
        BF4 hb, lb;
        #pragma unroll
        for (int e = 0; e < 4; e++) split2(o[4 * d4 + e] * inv, hb.v[e], lb.v[e]);
        *(BF4*)&Oh[obase + 4 * d4] = hb;
        *(BF4*)&Ol[obase + 4 * d4] = lb;
    }
}

// ---------------- launch -----------------------------------------------------
extern "C" void kernel_launch(void* const* d_in, const int* in_sizes, int n_in,
                              void* d_out, int out_size)
{
    const float* tokens = (const float*)d_in[0];
    const float* normw  = (const float*)d_in[1];
    const float* wq     = (const float*)d_in[2];
    const float* wk     = (const float*)d_in[3];
    const float* wv     = (const float*)d_in[4];
    const float* wo     = (const float*)d_in[5];
    float* out = (float*)d_out;

    __nv_bfloat16 *xh, *xl, *aoh, *aol;
    __nv_bfloat16 *wqh, *wql, *wkh, *wkl, *wvh, *wvl, *woh, *wol;
    float *q, *k, *v;
    cudaGetSymbolAddress((void**)&xh,  g_xh);
    cudaGetSymbolAddress((void**)&xl,  g_xl);
    cudaGetSymbolAddress((void**)&q,   g_q);
    cudaGetSymbolAddress((void**)&k,   g_k);
    cudaGetSymbolAddress((void**)&v,   g_v);
    cudaGetSymbolAddress((void**)&aoh, g_aoh);
    cudaGetSymbolAddress((void**)&aol, g_aol);
    cudaGetSymbolAddress((void**)&wqh, g_wqh);
    cudaGetSymbolAddress((void**)&wql, g_wql);
    cudaGetSymbolAddress((void**)&wkh, g_wkh);
    cudaGetSymbolAddress((void**)&wkl, g_wkl);
    cudaGetSymbolAddress((void**)&wvh, g_wvh);
    cudaGetSymbolAddress((void**)&wvl, g_wvl);
    cudaGetSymbolAddress((void**)&woh, g_woh);
    cudaGetSymbolAddress((void**)&wol, g_wol);

    cudaFuncSetAttribute(gemm_tc, cudaFuncAttributeMaxDynamicSharedMemorySize, GSMEM_DYN);

    rope_table_kernel<<<256, 256>>>();
    rmsnorm_split_kernel<<<MROWS, 256>>>(tokens, normw);

    int wblk = (DIM * DIM / 4) / 256;   // 1024 blocks
    split_w_kernel<<<wblk, 256>>>(wq, wqh, wql);
    split_w_kernel<<<wblk, 256>>>(wk, wkh, wkl);
    split_w_kernel<<<wblk, 256>>>(wv, wvh, wvl);
    split_w_kernel<<<wblk, 256>>>(wo, woh, wol);

    dim3 ggrid(DIM / 128, MROWS / 128);   // (8, 32)
    gemm_tc<<<ggrid, 256, GSMEM_DYN>>>(xh, xl, wqh, wql, q);
    gemm_tc<<<ggrid, 256, GSMEM_DYN>>>(xh, xl, wkh, wkl, k);
    gemm_tc<<<ggrid, 256, GSMEM_DYN>>>(xh, xl, wvh, wvl, v);

    int npairs = MROWS * (DIM / 2);
    rope_kernel<<<(npairs + 255) / 256, 256>>>(q, 0.125f);
    rope_kernel<<<(npairs + 255) / 256, 256>>>(k, 1.0f);

    flash_kernel<<<dim3(BATCH * NHEAD, N_TOK / BQ), 128>>>(q, k, v, aoh, aol);

    gemm_tc<<<ggrid, 256, GSMEM_DYN>>>(aoh, aol, woh, wol, out);
}

// round 5
// speedup vs baseline: 3.1541x; 1.8716x over previous
#include <cuda_runtime.h>
#include <cuda_bf16.h>
#include <math.h>
#include <stdint.h>

#define N_TOK 2048
#define BATCH 2
#define DIM   1024
#define NHEAD 16
#define DHEAD 64
#define MROWS (BATCH * N_TOK)   // 4096
#define RMS_EPS 1.1920929e-07f

// ---------------- scratch (static __device__ — no allocation) ----------------
__device__ __nv_bfloat16 g_xh [MROWS * DIM];
__device__ __nv_bfloat16 g_xl [MROWS * DIM];
__device__ float         g_q  [MROWS * DIM];
__device__ float         g_k  [MROWS * DIM];
__device__ float         g_v  [MROWS * DIM];
__device__ __nv_bfloat16 g_qh [MROWS * DIM], g_ql[MROWS * DIM];
__device__ __nv_bfloat16 g_kh [MROWS * DIM], g_kl[MROWS * DIM];
__device__ __nv_bfloat16 g_vh [MROWS * DIM], g_vl[MROWS * DIM];
__device__ __nv_bfloat16 g_aoh[MROWS * DIM];
__device__ __nv_bfloat16 g_aol[MROWS * DIM];
__device__ __nv_bfloat16 g_wqh[DIM * DIM], g_wql[DIM * DIM];
__device__ __nv_bfloat16 g_wkh[DIM * DIM], g_wkl[DIM * DIM];
__device__ __nv_bfloat16 g_wvh[DIM * DIM], g_wvl[DIM * DIM];
__device__ __nv_bfloat16 g_woh[DIM * DIM], g_wol[DIM * DIM];
__device__ float g_cos[N_TOK * (DHEAD / 2)];
__device__ float g_sin[N_TOK * (DHEAD / 2)];

// ---------------- helpers ----------------------------------------------------
__device__ __forceinline__ uint32_t smem_u32(const void* p) {
    uint32_t a;
    asm("{ .reg .u64 t; cvta.to.shared.u64 t, %1; cvt.u32.u64 %0, t; }" : "=r"(a) : "l"(p));
    return a;
}
__device__ __forceinline__ void cp_async16(uint32_t dst, const void* src) {
    asm volatile("cp.async.cg.shared.global [%0], [%1], 16;" :: "r"(dst), "l"(src));
}
#define CP_COMMIT() asm volatile("cp.async.commit_group;" ::: "memory")
#define CP_WAIT0()  asm volatile("cp.async.wait_group 0;" ::: "memory")
#define CP_WAIT1()  asm volatile("cp.async.wait_group 1;" ::: "memory")

__device__ __forceinline__ void ldmatrix_x4(uint32_t& r0, uint32_t& r1,
                                            uint32_t& r2, uint32_t& r3, uint32_t addr) {
    asm volatile("ldmatrix.sync.aligned.m8n8.x4.shared.b16 {%0,%1,%2,%3}, [%4];"
                 : "=r"(r0), "=r"(r1), "=r"(r2), "=r"(r3) : "r"(addr));
}
__device__ __forceinline__ void ldmatrix_x4_trans(uint32_t& r0, uint32_t& r1,
                                                  uint32_t& r2, uint32_t& r3, uint32_t addr) {
    asm volatile("ldmatrix.sync.aligned.m8n8.x4.trans.shared.b16 {%0,%1,%2,%3}, [%4];"
                 : "=r"(r0), "=r"(r1), "=r"(r2), "=r"(r3) : "r"(addr));
}
__device__ __forceinline__ void mma_bf16(float* d, const uint32_t* a, const uint32_t* b) {
    asm volatile(
        "mma.sync.aligned.m16n8k16.row.col.f32.bf16.bf16.f32 "
        "{%0,%1,%2,%3}, {%4,%5,%6,%7}, {%8,%9}, {%0,%1,%2,%3};"
        : "+f"(d[0]), "+f"(d[1]), "+f"(d[2]), "+f"(d[3])
        : "r"(a[0]), "r"(a[1]), "r"(a[2]), "r"(a[3]), "r"(b[0]), "r"(b[1]));
}
// pack two fp32 -> bf16x2 (lo in low half — matches mma k-pair order)
__device__ __forceinline__ uint32_t pack_bf(float lo, float hi) {
    uint32_t r;
    asm("cvt.rn.bf16x2.f32 %0, %1, %2;" : "=r"(r) : "f"(hi), "f"(lo));
    return r;
}

// fp32 -> (hi,lo) bf16 split
__device__ __forceinline__ void split2(float x, __nv_bfloat16& h, __nv_bfloat16& l) {
    h = __float2bfloat16(x);
    l = __float2bfloat16(x - __bfloat162float(h));
}
struct alignas(8) BF4 { __nv_bfloat16 v[4]; };

// ---------------- RoPE cos/sin table (fp64 trig: robust) ---------------------
__global__ void rope_table_kernel() {
    int idx = blockIdx.x * blockDim.x + threadIdx.x;   // t*32 + i
    if (idx >= N_TOK * 32) return;
    int t = idx >> 5;
    int i = idx & 31;
    double invf_d = pow(10000.0, -(double)(2 * i) / 64.0);
    float  invf   = (float)invf_d;
    float  ang    = (float)t * invf;
    g_cos[idx] = (float)cos((double)ang);
    g_sin[idx] = (float)sin((double)ang);
}

// ---------------- RMSNorm fused with bf16 hi/lo split ------------------------
__global__ __launch_bounds__(256) void rmsnorm_split_kernel(
    const float* __restrict__ x, const float* __restrict__ w)
{
    int row = blockIdx.x;
    const float4* xr = (const float4*)(x + (size_t)row * DIM);
    float4 v4 = xr[threadIdx.x];
    float ss = v4.x * v4.x + v4.y * v4.y + v4.z * v4.z + v4.w * v4.w;
    #pragma unroll
    for (int o = 16; o; o >>= 1) ss += __shfl_xor_sync(0xFFFFFFFFu, ss, o);
    __shared__ float sred[8];
    int lane = threadIdx.x & 31, wid = threadIdx.x >> 5;
    if (lane == 0) sred[wid] = ss;
    __syncthreads();
    if (wid == 0) {
        float t = (lane < 8) ? sred[lane] : 0.f;
        #pragma unroll
        for (int o = 4; o; o >>= 1) t += __shfl_xor_sync(0xFFFFFFFFu, t, o);
        if (lane == 0) sred[0] = t;
    }
    __syncthreads();
    float scale = rsqrtf(sred[0] * (1.0f / (float)DIM) + RMS_EPS);
    float4 wv = ((const float4*)w)[threadIdx.x];
    float o0 = v4.x * scale * wv.x, o1 = v4.y * scale * wv.y;
    float o2 = v4.z * scale * wv.z, o3 = v4.w * scale * wv.w;
    BF4 hb, lb;
    split2(o0, hb.v[0], lb.v[0]); split2(o1, hb.v[1], lb.v[1]);
    split2(o2, hb.v[2], lb.v[2]); split2(o3, hb.v[3], lb.v[3]);
    size_t base = (size_t)row * DIM + threadIdx.x * 4;
    *(BF4*)&g_xh[base] = hb;
    *(BF4*)&g_xl[base] = lb;
}

// ---------------- fp32 -> hi/lo bf16 split (weights, v) ----------------------
__global__ __launch_bounds__(256) void split_w_kernel(
    const float* __restrict__ w, __nv_bfloat16* __restrict__ wh, __nv_bfloat16* __restrict__ wl)
{
    int idx = blockIdx.x * blockDim.x + threadIdx.x;   // float4 index
    float4 v4 = ((const float4*)w)[idx];
    BF4 hb, lb;
    split2(v4.x, hb.v[0], lb.v[0]); split2(v4.y, hb.v[1], lb.v[1]);
    split2(v4.z, hb.v[2], lb.v[2]); split2(v4.w, hb.v[3], lb.v[3]);
    *(BF4*)&wh[(size_t)idx * 4] = hb;
    *(BF4*)&wl[(size_t)idx * 4] = lb;
}

// ---------------- RoPE + hi/lo split (q, k) ----------------------------------
__global__ void rope_split_kernel(const float* __restrict__ src, float qscale,
                                  __nv_bfloat16* __restrict__ dh, __nv_bfloat16* __restrict__ dl)
{
    int idx = blockIdx.x * blockDim.x + threadIdx.x;   // pair index
    if (idx >= MROWS * (DIM / 2)) return;
    int row = idx / (DIM / 2);
    int p   = idx % (DIM / 2);
    int pos = row & (N_TOK - 1);
    int i   = p & 31;
    float c = g_cos[pos * 32 + i];
    float s = g_sin[pos * 32 + i];
    float2 v = ((const float2*)src)[idx];
    float e = (v.x * c - v.y * s) * qscale;
    float o = (v.y * c + v.x * s) * qscale;
    __nv_bfloat162 hb, lb;
    split2(e, hb.x, lb.x);
    split2(o, hb.y, lb.y);
    ((__nv_bfloat162*)dh)[idx] = hb;
    ((__nv_bfloat162*)dl)[idx] = lb;
}

// ---------------- HMMA split-bf16 NT GEMM ------------------------------------
#define KC      32
#define ROWB    80
#define OPTILE  (128 * ROWB)
#define STAGEB  (4 * OPTILE)
#define NSTG    2
#define GSMEM_DYN (NSTG * STAGEB)
#define NCH     (DIM / KC)

__device__ __forceinline__ void load_stage(
    uint32_t sbase,
    const __nv_bfloat16* __restrict__ Ah, const __nv_bfloat16* __restrict__ Al,
    const __nv_bfloat16* __restrict__ Bh, const __nv_bfloat16* __restrict__ Bl,
    int bm, int bn, int kb, int tid)
{
    const __nv_bfloat16* srcs[4] = { Ah, Al, Bh, Bl };
    #pragma unroll
    for (int op = 0; op < 4; op++) {
        int r0 = (op < 2) ? bm : bn;
        const __nv_bfloat16* s = srcs[op];
        #pragma unroll
        for (int it = 0; it < 2; it++) {
            int i = tid + it * 256;
            int row = i >> 2, ch = i & 3;
            uint32_t dst = sbase + op * OPTILE + row * ROWB + ch * 16;
            cp_async16(dst, s + ((size_t)(r0 + row) * DIM + kb + ch * 8));
        }
    }
    CP_COMMIT();
}

__global__ __launch_bounds__(256, 2) void gemm_tc(
    const __nv_bfloat16* __restrict__ Ah, const __nv_bfloat16* __restrict__ Al,
    const __nv_bfloat16* __restrict__ Bh, const __nv_bfloat16* __restrict__ Bl,
    float* __restrict__ C)
{
    extern __shared__ char smem[];
    uint32_t sm0 = smem_u32(smem);
    int tid = threadIdx.x, wid = tid >> 5, lane = tid & 31;
    int bm = blockIdx.y * 128, bn = blockIdx.x * 128;
    int wm = wid >> 2, wn = wid & 3;

    float acc[4][4][4];
    #pragma unroll
    for (int i = 0; i < 4; i++)
        #pragma unroll
        for (int j = 0; j < 4; j++)
            #pragma unroll
            for (int e = 0; e < 4; e++) acc[i][j][e] = 0.f;

    int arow = wm * 64 + (lane & 15);
    int akb  = (lane >> 4) * 16;
    int brow = wn * 32 + ((lane >> 4) * 8) + (lane & 7);
    int bkb  = ((lane >> 3) & 1) * 16;

    load_stage(sm0, Ah, Al, Bh, Bl, bm, bn, 0, tid);

    for (int c = 0; c < NCH; c++) {
        CP_WAIT0();
        __syncthreads();
        uint32_t sb = sm0 + (c & 1) * STAGEB;
        if (c + 1 < NCH)
            load_stage(sm0 + ((c + 1) & 1) * STAGEB, Ah, Al, Bh, Bl, bm, bn, (c + 1) * KC, tid);

        uint32_t sAh = sb, sAl = sb + OPTILE, sBh = sb + 2 * OPTILE, sBl = sb + 3 * OPTILE;
        #pragma unroll
        for (int kk = 0; kk < 2; kk++) {
            uint32_t ah[4][4], al[4][4], bh[4][2], bl[4][2];
            #pragma unroll
            for (int mt = 0; mt < 4; mt++) {
                uint32_t ao = (uint32_t)((arow + mt * 16) * ROWB + kk * 32 + akb);
                ldmatrix_x4(ah[mt][0], ah[mt][1], ah[mt][2], ah[mt][3], sAh + ao);
                ldmatrix_x4(al[mt][0], al[mt][1], al[mt][2], al[mt][3], sAl + ao);
            }
            #pragma unroll
            for (int p = 0; p < 2; p++) {
                uint32_t bo = (uint32_t)((brow + p * 16) * ROWB + kk * 32 + bkb);
                uint32_t r0, r1, r2, r3;
                ldmatrix_x4(r0, r1, r2, r3, sBh + bo);
                bh[p * 2][0] = r0; bh[p * 2][1] = r1; bh[p * 2 + 1][0] = r2; bh[p * 2 + 1][1] = r3;
                ldmatrix_x4(r0, r1, r2, r3, sBl + bo);
                bl[p * 2][0] = r0; bl[p * 2][1] = r1; bl[p * 2 + 1][0] = r2; bl[p * 2 + 1][1] = r3;
            }
            #pragma unroll
            for (int mt = 0; mt < 4; mt++)
                #pragma unroll
                for (int nt = 0; nt < 4; nt++) {
                    mma_bf16(acc[mt][nt], ah[mt], bh[nt]);
                    mma_bf16(acc[mt][nt], ah[mt], bl[nt]);
                    mma_bf16(acc[mt][nt], al[mt], bh[nt]);
                }
        }
        __syncthreads();
    }

    int r = lane >> 2, cp = (lane & 3) * 2;
    #pragma unroll
    for (int mt = 0; mt < 4; mt++) {
        int gm = bm + wm * 64 + mt * 16 + r;
        #pragma unroll
        for (int nt = 0; nt < 4; nt++) {
            int gc = bn + wn * 32 + nt * 8 + cp;
            *(float2*)(C + (size_t)gm * DIM + gc) =
                make_float2(acc[mt][nt][0], acc[mt][nt][1]);
            *(float2*)(C + (size_t)(gm + 8) * DIM + gc) =
                make_float2(acc[mt][nt][2], acc[mt][nt][3]);
        }
    }
}

// ---------------- HMMA split-bf16 causal flash attention ---------------------
// Per CTA: one (b,h), 64 q rows (4 warps x m16). j-tiles of 64 keys.
#define FROW   144                    // 64 bf16 = 128 B + 16 B pad
#define FTILE  (64 * FROW)            // 9216 B
#define FSTAGE (4 * FTILE)            // Kh,Kl,Vh,Vl = 36864 B
#define FQOFF  (2 * FSTAGE)           // 73728
#define FSMEM  (FQOFF + 2 * FTILE)    // 92160

__device__ __forceinline__ void flash_load_kv(
    uint32_t sbase,
    const __nv_bfloat16* __restrict__ kh, const __nv_bfloat16* __restrict__ kl,
    const __nv_bfloat16* __restrict__ vh, const __nv_bfloat16* __restrict__ vl,
    int grow0, int h, int tid)
{
    const __nv_bfloat16* srcs[4] = { kh, kl, vh, vl };
    #pragma unroll
    for (int t = 0; t < 16; t++) {
        int i = tid + t * 128;          // 0..2047
        int tile = i >> 9;
        int r = (i >> 3) & 63;
        int ch = i & 7;
        uint32_t dst = sbase + tile * FTILE + r * FROW + ch * 16;
        cp_async16(dst, srcs[tile] + ((size_t)(grow0 + r) * DIM + h * DHEAD + ch * 8));
    }
}

__global__ __launch_bounds__(128) void flash_tc(
    const __nv_bfloat16* __restrict__ Qh, const __nv_bfloat16* __restrict__ Ql,
    const __nv_bfloat16* __restrict__ Kh, const __nv_bfloat16* __restrict__ Kl,
    const __nv_bfloat16* __restrict__ Vh, const __nv_bfloat16* __restrict__ Vl,
    __nv_bfloat16* __restrict__ Oh, __nv_bfloat16* __restrict__ Ol)
{
    extern __shared__ char smem[];
    uint32_t sm0 = smem_u32(smem);
    int tid = threadIdx.x, w = tid >> 5, lane = tid & 31;
    int bh = blockIdx.x;
    int b  = bh >> 4, h = bh & 15;
    int r0 = ((int)gridDim.y - 1 - (int)blockIdx.y) * 64;
    int ntiles = r0 / 64 + 1;
    int growq = b * N_TOK + r0;

    // ---- initial loads: Q tile + KV stage 0 (group 0), KV stage 1 (group 1)
    {
        const __nv_bfloat16* qs[2] = { Qh, Ql };
        #pragma unroll
        for (int t = 0; t < 8; t++) {
            int i = tid + t * 128;      // 0..1023
            int hl = i >> 9;
            int r = (i >> 3) & 63;
            int ch = i & 7;
            uint32_t dst = sm0 + FQOFF + hl * FTILE + r * FROW + ch * 16;
            cp_async16(dst, qs[hl] + ((size_t)(growq + r) * DIM + h * DHEAD + ch * 8));
        }
        flash_load_kv(sm0, Kh, Kl, Vh, Vl, b * N_TOK, h, tid);
        CP_COMMIT();
        if (ntiles > 1) {
            flash_load_kv(sm0 + FSTAGE, Kh, Kl, Vh, Vl, b * N_TOK + 64, h, tid);
            CP_COMMIT();
        }
    }

    uint32_t qhf[4][4], qlf[4][4];
    float oacc[8][4];
    #pragma unroll
    for (int nt = 0; nt < 8; nt++)
        #pragma unroll
        for (int e = 0; e < 4; e++) oacc[nt][e] = 0.f;
    float m0 = -1e30f, m1 = -1e30f, l0 = 0.f, l1 = 0.f;

    for (int t = 0; t < ntiles; t++) {
        if (t + 1 < ntiles) { CP_WAIT1(); } else { CP_WAIT0(); }
        __syncthreads();

        if (t == 0) {   // Q fragments (once)
            uint32_t qb = sm0 + FQOFF + (uint32_t)((w * 16 + (lane & 15)) * FROW + (lane >> 4) * 16);
            #pragma unroll
            for (int kt = 0; kt < 4; kt++) {
                ldmatrix_x4(qhf[kt][0], qhf[kt][1], qhf[kt][2], qhf[kt][3], qb + kt * 32);
                ldmatrix_x4(qlf[kt][0], qlf[kt][1], qlf[kt][2], qlf[kt][3], qb + FTILE + kt * 32);
            }
        }

        uint32_t sb = sm0 + (uint32_t)(t & 1) * FSTAGE;

        // ---- S = Q K^T (3-pass) ----
        float sacc[8][4];
        #pragma unroll
        for (int nt = 0; nt < 8; nt++)
            #pragma unroll
            for (int e = 0; e < 4; e++) sacc[nt][e] = 0.f;

        uint32_t kb = sb + (uint32_t)(((lane & 7) + ((lane >> 4) & 1) * 8) * FROW + ((lane >> 3) & 1) * 16);
        #pragma unroll
        for (int kt = 0; kt < 4; kt++)
            #pragma unroll
            for (int jg = 0; jg < 4; jg++) {
                uint32_t addr = kb + (uint32_t)(jg * 16 * FROW + kt * 32);
                uint32_t bhh[4], bll[4];
                ldmatrix_x4(bhh[0], bhh[1], bhh[2], bhh[3], addr);
                ldmatrix_x4(bll[0], bll[1], bll[2], bll[3], addr + FTILE);
                mma_bf16(sacc[2 * jg],     qhf[kt], &bhh[0]);
                mma_bf16(sacc[2 * jg],     qhf[kt], &bll[0]);
                mma_bf16(sacc[2 * jg],     qlf[kt], &bhh[0]);
                mma_bf16(sacc[2 * jg + 1], qhf[kt], &bhh[2]);
                mma_bf16(sacc[2 * jg + 1], qhf[kt], &bll[2]);
                mma_bf16(sacc[2 * jg + 1], qlf[kt], &bhh[2]);
            }

        // ---- causal mask (only diagonal tile) ----
        if (t == ntiles - 1) {
            int i0 = r0 + w * 16 + (lane >> 2);   // row for elems 0,1; +8 for 2,3
            int j0 = t * 64 + (lane & 3) * 2;
            #pragma unroll
            for (int nt = 0; nt < 8; nt++) {
                int jc = j0 + nt * 8;
                if (jc     > i0)     sacc[nt][0] = -1e30f;
                if (jc + 1 > i0)     sacc[nt][1] = -1e30f;
                if (jc     > i0 + 8) sacc[nt][2] = -1e30f;
                if (jc + 1 > i0 + 8) sacc[nt][3] = -1e30f;
            }
        }

        // ---- online softmax ----
        float mx0 = -1e30f, mx1 = -1e30f;
        #pragma unroll
        for (int nt = 0; nt < 8; nt++) {
            mx0 = fmaxf(mx0, fmaxf(sacc[nt][0], sacc[nt][1]));
            mx1 = fmaxf(mx1, fmaxf(sacc[nt][2], sacc[nt][3]));
        }
        mx0 = fmaxf(mx0, __shfl_xor_sync(0xFFFFFFFFu, mx0, 1));
        mx0 = fmaxf(mx0, __shfl_xor_sync(0xFFFFFFFFu, mx0, 2));
        mx1 = fmaxf(mx1, __shfl_xor_sync(0xFFFFFFFFu, mx1, 1));
        mx1 = fmaxf(mx1, __shfl_xor_sync(0xFFFFFFFFu, mx1, 2));
        float mn0 = fmaxf(m0, mx0), mn1 = fmaxf(m1, mx1);
        float sc0 = __expf(m0 - mn0), sc1 = __expf(m1 - mn1);
        l0 *= sc0; l1 *= sc1;
        #pragma unroll
        for (int nt = 0; nt < 8; nt++) {
            oacc[nt][0] *= sc0; oacc[nt][1] *= sc0;
            oacc[nt][2] *= sc1; oacc[nt][3] *= sc1;
        }
        float su0 = 0.f, su1 = 0.f;
        #pragma unroll
        for (int nt = 0; nt < 8; nt++) {
            float p0 = __expf(sacc[nt][0] - mn0);
            float p1 = __expf(sacc[nt][1] - mn0);
            float p2 = __expf(sacc[nt][2] - mn1);
            float p3 = __expf(sacc[nt][3] - mn1);
            sacc[nt][0] = p0; sacc[nt][1] = p1; sacc[nt][2] = p2; sacc[nt][3] = p3;
            su0 += p0 + p1; su1 += p2 + p3;
        }
        su0 += __shfl_xor_sync(0xFFFFFFFFu, su0, 1);
        su0 += __shfl_xor_sync(0xFFFFFFFFu, su0, 2);
        su1 += __shfl_xor_sync(0xFFFFFFFFu, su1, 1);
        su1 += __shfl_xor_sync(0xFFFFFFFFu, su1, 2);
        l0 += su0; l1 += su1;
        m0 = mn0; m1 = mn1;

        // ---- O += P V (3-pass) ----
        uint32_t vb = sb + 2 * FTILE
                    + (uint32_t)(((lane & 7) + ((lane >> 3) & 1) * 8) * FROW + ((lane >> 4) & 1) * 16);
        #pragma unroll
        for (int kt = 0; kt < 4; kt++) {
            int t0 = 2 * kt, t1 = 2 * kt + 1;
            float ph[8], pl[8];
            #pragma unroll
            for (int e = 0; e < 4; e++) {
                float p = sacc[t0][e];
                float hh = __bfloat162float(__float2bfloat16(p));
                ph[e] = hh; pl[e] = p - hh;
                p = sacc[t1][e];
                hh = __bfloat162float(__float2bfloat16(p));
                ph[4 + e] = hh; pl[4 + e] = p - hh;
            }
            uint32_t pa_h[4], pa_l[4];
            pa_h[0] = pack_bf(ph[0], ph[1]); pa_h[1] = pack_bf(ph[2], ph[3]);
            pa_h[2] = pack_bf(ph[4], ph[5]); pa_h[3] = pack_bf(ph[6], ph[7]);
            pa_l[0] = pack_bf(pl[0], pl[1]); pa_l[1] = pack_bf(pl[2], pl[3]);
            pa_l[2] = pack_bf(pl[4], pl[5]); pa_l[3] = pack_bf(pl[6], pl[7]);

            #pragma unroll
            for (int dp = 0; dp < 4; dp++) {
                uint32_t addr = vb + (uint32_t)(kt * 16 * FROW + dp * 32);
                uint32_t vhh[4], vll[4];
                ldmatrix_x4_trans(vhh[0], vhh[1], vhh[2], vhh[3], addr);
                ldmatrix_x4_trans(vll[0], vll[1], vll[2], vll[3], addr + FTILE);
                mma_bf16(oacc[2 * dp],     pa_h, &vhh[0]);
                mma_bf16(oacc[2 * dp],     pa_h, &vll[0]);
                mma_bf16(oacc[2 * dp],     pa_l, &vhh[0]);
                mma_bf16(oacc[2 * dp + 1], pa_h, &vhh[2]);
                mma_bf16(oacc[2 * dp + 1], pa_h, &vll[2]);
                mma_bf16(oacc[2 * dp + 1], pa_l, &vhh[2]);
            }
        }

        __syncthreads();
        if (t + 2 < ntiles) {
            flash_load_kv(sm0 + (uint32_t)(t & 1) * FSTAGE, Kh, Kl, Vh, Vl,
                          b * N_TOK + (t + 2) * 64, h, tid);
            CP_COMMIT();
        }
    }

    // ---- epilogue: divide by l, split to hi/lo bf16, store ----
    float inv0 = 1.f / l0, inv1 = 1.f / l1;
    int gr = b * N_TOK + r0 + w * 16 + (lane >> 2);
    int gc = h * DHEAD + (lane & 3) * 2;
    #pragma unroll
    for (int nt = 0; nt < 8; nt++) {
        float a0 = oacc[nt][0] * inv0, a1 = oacc[nt][1] * inv0;
        float a2 = oacc[nt][2] * inv1, a3 = oacc[nt][3] * inv1;
        __nv_bfloat162 hb, lb;
        split2(a0, hb.x, lb.x); split2(a1, hb.y, lb.y);
        size_t o0 = (size_t)gr * DIM + gc + nt * 8;
        *(__nv_bfloat162*)&Oh[o0] = hb;
        *(__nv_bfloat162*)&Ol[o0] = lb;
        split2(a2, hb.x, lb.x); split2(a3, hb.y, lb.y);
        size_t o1 = (size_t)(gr + 8) * DIM + gc + nt * 8;
        *(__nv_bfloat162*)&Oh[o1] = hb;
        *(__nv_bfloat162*)&Ol[o1] = lb;
    }
}

// ---------------- launch -----------------------------------------------------
extern "C" void kernel_launch(void* const* d_in, const int* in_sizes, int n_in,
                              void* d_out, int out_size)
{
    const float* tokens = (const float*)d_in[0];
    const float* normw  = (const float*)d_in[1];
    const float* wq     = (const float*)d_in[2];
    const float* wk     = (const float*)d_in[3];
    const float* wv     = (const float*)d_in[4];
    const float* wo     = (const float*)d_in[5];
    float* out = (float*)d_out;

    __nv_bfloat16 *xh, *xl, *aoh, *aol;
    __nv_bfloat16 *qh, *ql, *kh, *kl, *vh, *vl;
    __nv_bfloat16 *wqh, *wql, *wkh, *wkl, *wvh, *wvl, *woh, *wol;
    float *q, *k, *v;
    cudaGetSymbolAddress((void**)&xh,  g_xh);
    cudaGetSymbolAddress((void**)&xl,  g_xl);
    cudaGetSymbolAddress((void**)&q,   g_q);
    cudaGetSymbolAddress((void**)&k,   g_k);
    cudaGetSymbolAddress((void**)&v,   g_v);
    cudaGetSymbolAddress((void**)&qh,  g_qh);
    cudaGetSymbolAddress((void**)&ql,  g_ql);
    cudaGetSymbolAddress((void**)&kh,  g_kh);
    cudaGetSymbolAddress((void**)&kl,  g_kl);
    cudaGetSymbolAddress((void**)&vh,  g_vh);
    cudaGetSymbolAddress((void**)&vl,  g_vl);
    cudaGetSymbolAddress((void**)&aoh, g_aoh);
    cudaGetSymbolAddress((void**)&aol, g_aol);
    cudaGetSymbolAddress((void**)&wqh, g_wqh);
    cudaGetSymbolAddress((void**)&wql, g_wql);
    cudaGetSymbolAddress((void**)&wkh, g_wkh);
    cudaGetSymbolAddress((void**)&wkl, g_wkl);
    cudaGetSymbolAddress((void**)&wvh, g_wvh);
    cudaGetSymbolAddress((void**)&wvl, g_wvl);
    cudaGetSymbolAddress((void**)&woh, g_woh);
    cudaGetSymbolAddress((void**)&wol, g_wol);

    cudaFuncSetAttribute(gemm_tc,  cudaFuncAttributeMaxDynamicSharedMemorySize, GSMEM_DYN);
    cudaFuncSetAttribute(flash_tc, cudaFuncAttributeMaxDynamicSharedMemorySize, FSMEM);

    rope_table_kernel<<<256, 256>>>();
    rmsnorm_split_kernel<<<MROWS, 256>>>(tokens, normw);

    int wblk = (DIM * DIM / 4) / 256;   // 1024 blocks
    split_w_kernel<<<wblk, 256>>>(wq, wqh, wql);
    split_w_kernel<<<wblk, 256>>>(wk, wkh, wkl);
    split_w_kernel<<<wblk, 256>>>(wv, wvh, wvl);
    split_w_kernel<<<wblk, 256>>>(wo, woh, wol);

    dim3 ggrid(DIM / 128, MROWS / 128);   // (8, 32)
    gemm_tc<<<ggrid, 256, GSMEM_DYN>>>(xh, xl, wqh, wql, q);
    gemm_tc<<<ggrid, 256, GSMEM_DYN>>>(xh, xl, wkh, wkl, k);
    gemm_tc<<<ggrid, 256, GSMEM_DYN>>>(xh, xl, wvh, wvl, v);

    int npairs = MROWS * (DIM / 2);
    rope_split_kernel<<<(npairs + 255) / 256, 256>>>(q, 0.125f, qh, ql);
    rope_split_kernel<<<(npairs + 255) / 256, 256>>>(k, 1.0f,  kh, kl);
    split_w_kernel<<<(MROWS * DIM / 4) / 256, 256>>>(v, vh, vl);   // 4096 blocks

    flash_tc<<<dim3(BATCH * NHEAD, N_TOK / 64), 128, FSMEM>>>(qh, ql, kh, kl, vh, vl, aoh, aol);

    gemm_tc<<<ggrid, 256, GSMEM_DYN>>>(aoh, aol, woh, wol, out);
}